// round 1
// baseline (speedup 1.0000x reference)
#include <cuda_runtime.h>
#include <cuda_bf16.h>
#include <cstdint>

#define BB 16
#define TT 4096
#define TRR 4088
#define DD 768
#define NSS_ 8
#define INNER_ 192
#define DKK 1536
#define SIM_SCALE 0.03608439182435161f  /* 1/sqrt(768) */

// ---------------- scratch (__device__ globals; no allocation allowed) -------
__device__ float g_meansum[BB * DD];
__device__ float g_newss[BB * NSS_ * DD];
__device__ float g_wqss[BB * DD * NSS_];   // [b][d][s]
__device__ float g_qb[BB * NSS_];
__device__ float g_attn[(size_t)BB * TRR * NSS_];
__device__ uint4 g_ahi4[(size_t)BB * TRR * DD / 8];   // bf16 hi of reg
__device__ uint4 g_alo4[(size_t)BB * TRR * DD / 8];   // bf16 lo of reg
__device__ uint4 g_wvThi4[DD * DD / 8];               // WvT [n][k] bf16 hi
__device__ uint4 g_wvTlo4[DD * DD / 8];               // WvT [n][k] bf16 lo

// ---------------- k_zero: clear mean accumulator ----------------------------
__global__ void k_zero() {
    int i = blockIdx.x * 256 + threadIdx.x;
    if (i < BB * DD) g_meansum[i] = 0.f;
}

// ------- k_convert_mean: fp32 -> bf16 hi/lo split + column-mean partials ----
// grid (64 chunks, 16 batches), 192 threads; each thread owns 4 contiguous d.
__global__ void __launch_bounds__(192) k_convert_mean(const float* __restrict__ x) {
    int b = blockIdx.y, c = blockIdx.x, tid = threadIdx.x;
    int d0 = tid * 4;
    __nv_bfloat16* ah = (__nv_bfloat16*)g_ahi4;
    __nv_bfloat16* al = (__nv_bfloat16*)g_alo4;
    float a0 = 0.f, a1 = 0.f, a2 = 0.f, a3 = 0.f;
    int t0 = c * 64;
    int tend = t0 + 64; if (tend > TRR) tend = TRR;
    for (int t = t0; t < tend; t++) {
        const float4 v = *(const float4*)(x + ((size_t)(b * TT + t)) * DD + d0);
        __nv_bfloat16 h0 = __float2bfloat16(v.x);
        __nv_bfloat16 h1 = __float2bfloat16(v.y);
        __nv_bfloat16 h2 = __float2bfloat16(v.z);
        __nv_bfloat16 h3 = __float2bfloat16(v.w);
        __nv_bfloat16 l0 = __float2bfloat16(v.x - __bfloat162float(h0));
        __nv_bfloat16 l1 = __float2bfloat16(v.y - __bfloat162float(h1));
        __nv_bfloat16 l2 = __float2bfloat16(v.z - __bfloat162float(h2));
        __nv_bfloat16 l3 = __float2bfloat16(v.w - __bfloat162float(h3));
        uint2 hp, lp;
        hp.x = (uint32_t)__bfloat16_as_ushort(h0) | ((uint32_t)__bfloat16_as_ushort(h1) << 16);
        hp.y = (uint32_t)__bfloat16_as_ushort(h2) | ((uint32_t)__bfloat16_as_ushort(h3) << 16);
        lp.x = (uint32_t)__bfloat16_as_ushort(l0) | ((uint32_t)__bfloat16_as_ushort(l1) << 16);
        lp.y = (uint32_t)__bfloat16_as_ushort(l2) | ((uint32_t)__bfloat16_as_ushort(l3) << 16);
        size_t idx = ((size_t)(b * TRR + t)) * DD + d0;
        *(uint2*)(ah + idx) = hp;
        *(uint2*)(al + idx) = lp;
        a0 += v.x; a1 += v.y; a2 += v.z; a3 += v.w;
    }
    atomicAdd(&g_meansum[b * DD + d0 + 0], a0);
    atomicAdd(&g_meansum[b * DD + d0 + 1], a1);
    atomicAdd(&g_meansum[b * DD + d0 + 2], a2);
    atomicAdd(&g_meansum[b * DD + d0 + 3], a3);
}

// ------- k_convert_wv: split Wv to bf16 hi/lo, transposed [n][k] ------------
__global__ void k_convert_wv(const float* __restrict__ Wv) {
    int k = blockIdx.x;  // 768 rows
    __nv_bfloat16* th = (__nv_bfloat16*)g_wvThi4;
    __nv_bfloat16* tl = (__nv_bfloat16*)g_wvTlo4;
    for (int n = threadIdx.x; n < DD; n += 256) {
        float v = Wv[k * DD + n];
        __nv_bfloat16 h = __float2bfloat16(v);
        __nv_bfloat16 l = __float2bfloat16(v - __bfloat162float(h));
        th[n * DD + k] = h;
        tl[n * DD + k] = l;
    }
}

// ------- k_prep: ss_update, new_ss, output tail rows, qb --------------------
// grid (8 s, 16 b), 256 threads.
__global__ void __launch_bounds__(256) k_prep(
    const float* __restrict__ x, const float* __restrict__ Wk,
    const float* __restrict__ bk, const float* __restrict__ Wss,
    const float* __restrict__ bss, const float* __restrict__ bq,
    float* __restrict__ out) {
    int s = blockIdx.x, b = blockIdx.y, tid = threadIdx.x;
    __shared__ float sm[DD];
    __shared__ float su[INNER_];
    __shared__ float red[8];
    for (int d = tid; d < DD; d += 256)
        sm[d] = g_meansum[b * DD + d] * (1.0f / (float)TRR);
    __syncthreads();
    if (tid < INNER_) {
        float a = bk[s * INNER_ + tid];
        #pragma unroll 8
        for (int d = 0; d < DD; d++)
            a += sm[d] * Wk[d * DKK + s * INNER_ + tid];
        su[tid] = a;
    }
    __syncthreads();
    float nv[3];
    #pragma unroll
    for (int kk = 0; kk < 3; kk++) {
        int j = tid + kk * 256;
        float a = bss[j] + x[((size_t)(b * TT + TRR + s)) * DD + j];
        #pragma unroll 8
        for (int i = 0; i < INNER_; i++)
            a += su[i] * Wss[i * DD + j];
        nv[kk] = a;
    }
    #pragma unroll
    for (int kk = 0; kk < 3; kk++) {
        int j = tid + kk * 256;
        g_newss[(b * NSS_ + s) * DD + j] = nv[kk];
        out[((size_t)(b * TT + TRR + s)) * DD + j] = nv[kk];
    }
    // qb[b][s] = bq . new_ss[b][s]
    float p = 0.f;
    #pragma unroll
    for (int kk = 0; kk < 3; kk++) p += bq[tid + kk * 256] * nv[kk];
    #pragma unroll
    for (int off = 16; off > 0; off >>= 1) p += __shfl_xor_sync(0xffffffffu, p, off);
    if ((tid & 31) == 0) red[tid >> 5] = p;
    __syncthreads();
    if (tid == 0) {
        float q = 0.f;
        #pragma unroll
        for (int w = 0; w < 8; w++) q += red[w];
        g_qb[b * NSS_ + s] = q;
    }
}

// ------- k_wqss: Wq_ss[b][d][s] = sum_j Wq[d][j] * new_ss[b][s][j] ----------
// grid (24 d-tiles, 16 b), 256 threads: tid -> (s = tid&7, d = d0 + tid>>3)
__global__ void __launch_bounds__(256) k_wqss(const float* __restrict__ Wq) {
    int b = blockIdx.y, d0 = blockIdx.x * 32, tid = threadIdx.x;
    __shared__ float sn[NSS_ * 772];  // pitch 772 -> conflict-free across s
    for (int i = tid; i < NSS_ * DD; i += 256) {
        int s = i / DD, j = i - s * DD;
        sn[s * 772 + j] = g_newss[(b * NSS_ + s) * DD + j];
    }
    __syncthreads();
    int s = tid & 7, d = d0 + (tid >> 3);
    const float* wr = Wq + (size_t)d * DD;
    const float* nr = sn + s * 772;
    float a = 0.f;
    #pragma unroll 8
    for (int j = 0; j < DD; j++) a += wr[j] * nr[j];
    g_wqss[(b * DD + d) * NSS_ + s] = a;
}

// ------- k_attn: sim + softmax, warp handles 8 consecutive tokens -----------
__global__ void __launch_bounds__(256) k_attn() {
    int warp = (blockIdx.x * blockDim.x + threadIdx.x) >> 5;
    int lane = threadIdx.x & 31;
    if (warp >= BB * (TRR / 8)) return;
    int b = warp / (TRR / 8);
    int tok0 = (warp - b * (TRR / 8)) * 8;
    const __nv_bfloat16* ah = (const __nv_bfloat16*)g_ahi4;
    const __nv_bfloat16* al = (const __nv_bfloat16*)g_alo4;
    size_t base = ((size_t)(b * TRR + tok0)) * DD;
    const float4* wq = (const float4*)(g_wqss + (size_t)b * DD * NSS_);
    float sim[8][8];
    #pragma unroll
    for (int j = 0; j < 8; j++)
        #pragma unroll
        for (int s = 0; s < 8; s++) sim[j][s] = 0.f;
    #pragma unroll 2
    for (int i = 0; i < 24; i++) {
        int d = lane + i * 32;
        float4 w0 = wq[d * 2], w1 = wq[d * 2 + 1];
        float v[8];
        #pragma unroll
        for (int j = 0; j < 8; j++) {
            size_t idx = base + (size_t)j * DD + d;
            v[j] = __bfloat162float(ah[idx]) + __bfloat162float(al[idx]);
        }
        #pragma unroll
        for (int j = 0; j < 8; j++) {
            sim[j][0] += v[j] * w0.x; sim[j][1] += v[j] * w0.y;
            sim[j][2] += v[j] * w0.z; sim[j][3] += v[j] * w0.w;
            sim[j][4] += v[j] * w1.x; sim[j][5] += v[j] * w1.y;
            sim[j][6] += v[j] * w1.z; sim[j][7] += v[j] * w1.w;
        }
    }
    #pragma unroll
    for (int j = 0; j < 8; j++)
        #pragma unroll
        for (int s = 0; s < 8; s++)
            #pragma unroll
            for (int off = 16; off > 0; off >>= 1)
                sim[j][s] += __shfl_xor_sync(0xffffffffu, sim[j][s], off);
    if (lane < 8) {
        int j = lane;
        float p[8], m = -1e30f;
        #pragma unroll
        for (int s = 0; s < 8; s++) {
            p[s] = (sim[j][s] + g_qb[b * NSS_ + s]) * SIM_SCALE;
            m = fmaxf(m, p[s]);
        }
        float sum = 0.f;
        #pragma unroll
        for (int s = 0; s < 8; s++) { p[s] = expf(p[s] - m); sum += p[s]; }
        float inv = 1.f / sum;
        size_t ro = ((size_t)(b * TRR + tok0 + j)) * NSS_;
        #pragma unroll
        for (int s = 0; s < 8; s++) g_attn[ro + s] = p[s] * inv;
    }
}

// ------- k_main: split-bf16 GEMM (reg @ Wv) + fused attention epilogue ------
#define MMA_BF16(Cr, Ar, Br)                                                   \
    asm volatile(                                                              \
        "mma.sync.aligned.m16n8k16.row.col.f32.bf16.bf16.f32 "                 \
        "{%0,%1,%2,%3},{%4,%5,%6,%7},{%8,%9},{%0,%1,%2,%3};\n"                 \
        : "+f"(Cr[0]), "+f"(Cr[1]), "+f"(Cr[2]), "+f"(Cr[3])                   \
        : "r"(Ar[0]), "r"(Ar[1]), "r"(Ar[2]), "r"(Ar[3]), "r"(Br[0]), "r"(Br[1]))

__global__ void __launch_bounds__(256) k_main(const float* __restrict__ bv,
                                              float* __restrict__ out) {
    extern __shared__ __align__(16) unsigned char smraw[];
    __nv_bfloat16* Ah = (__nv_bfloat16*)smraw;   // [2][128*40]
    __nv_bfloat16* Al = Ah + 2 * 5120;
    __nv_bfloat16* Bh = Al + 2 * 5120;
    __nv_bfloat16* Bl = Bh + 2 * 5120;
    const int b = blockIdx.z, t0 = blockIdx.y * 128, n0 = blockIdx.x * 128;
    const int tid = threadIdx.x, lane = tid & 31, wid = tid >> 5;
    const int wm = wid >> 2, wn = wid & 3;
    const __nv_bfloat16* gAh = (const __nv_bfloat16*)g_ahi4;
    const __nv_bfloat16* gAl = (const __nv_bfloat16*)g_alo4;
    const __nv_bfloat16* gBh = (const __nv_bfloat16*)g_wvThi4;
    const __nv_bfloat16* gBl = (const __nv_bfloat16*)g_wvTlo4;

    float acc[4][4][4];
    #pragma unroll
    for (int mi = 0; mi < 4; mi++)
        #pragma unroll
        for (int ni = 0; ni < 4; ni++)
            #pragma unroll
            for (int q = 0; q < 4; q++) acc[mi][ni][q] = 0.f;

    for (int kt = 0; kt < 24; kt++) {
        const int k0 = kt * 32, buf = kt & 1;
        #pragma unroll
        for (int i = 0; i < 2; i++) {
            int c = tid + i * 256;
            int row = c >> 2, kc = (c & 3) * 8;
            int t = t0 + row;
            uint4 va = make_uint4(0, 0, 0, 0), vl = va;
            if (t < TRR) {
                size_t gi = ((size_t)(b * TRR + t)) * DD + k0 + kc;
                va = *(const uint4*)(gAh + gi);
                vl = *(const uint4*)(gAl + gi);
            }
            *(uint4*)(Ah + buf * 5120 + row * 40 + kc) = va;
            *(uint4*)(Al + buf * 5120 + row * 40 + kc) = vl;
            size_t bi = ((size_t)(n0 + row)) * DD + k0 + kc;
            *(uint4*)(Bh + buf * 5120 + row * 40 + kc) = *(const uint4*)(gBh + bi);
            *(uint4*)(Bl + buf * 5120 + row * 40 + kc) = *(const uint4*)(gBl + bi);
        }
        __syncthreads();
        const __nv_bfloat16* As = Ah + buf * 5120;
        const __nv_bfloat16* Als = Al + buf * 5120;
        const __nv_bfloat16* Bs = Bh + buf * 5120;
        const __nv_bfloat16* Bls = Bl + buf * 5120;
        #pragma unroll
        for (int kk = 0; kk < 32; kk += 16) {
            uint32_t ra[4][4], la[4][4];
            #pragma unroll
            for (int mi = 0; mi < 4; mi++) {
                int r = wm * 64 + mi * 16 + (lane >> 2);
                int cc = kk + (lane & 3) * 2;
                const __nv_bfloat16* p = As + r * 40 + cc;
                ra[mi][0] = *(const uint32_t*)(p);
                ra[mi][1] = *(const uint32_t*)(p + 8 * 40);
                ra[mi][2] = *(const uint32_t*)(p + 8);
                ra[mi][3] = *(const uint32_t*)(p + 8 * 40 + 8);
                const __nv_bfloat16* q = Als + r * 40 + cc;
                la[mi][0] = *(const uint32_t*)(q);
                la[mi][1] = *(const uint32_t*)(q + 8 * 40);
                la[mi][2] = *(const uint32_t*)(q + 8);
                la[mi][3] = *(const uint32_t*)(q + 8 * 40 + 8);
            }
            uint32_t rb[4][2], lb[4][2];
            #pragma unroll
            for (int ni = 0; ni < 4; ni++) {
                int n = wn * 32 + ni * 8 + (lane >> 2);
                int kb = kk + (lane & 3) * 2;
                const __nv_bfloat16* p = Bs + n * 40 + kb;
                rb[ni][0] = *(const uint32_t*)(p);
                rb[ni][1] = *(const uint32_t*)(p + 8);
                const __nv_bfloat16* q = Bls + n * 40 + kb;
                lb[ni][0] = *(const uint32_t*)(q);
                lb[ni][1] = *(const uint32_t*)(q + 8);
            }
            #pragma unroll
            for (int mi = 0; mi < 4; mi++)
                #pragma unroll
                for (int ni = 0; ni < 4; ni++) {
                    MMA_BF16(acc[mi][ni], ra[mi], rb[ni]);
                    MMA_BF16(acc[mi][ni], ra[mi], lb[ni]);
                    MMA_BF16(acc[mi][ni], la[mi], rb[ni]);
                }
        }
        __syncthreads();
    }

    // ---- epilogue: relu(acc + bv + attn @ new_ss) ----
    float* at_s = (float*)smraw;        // [128][8]
    float* ss_s = at_s + 128 * 8;       // [8][128]
    float* bv_s = ss_s + 8 * 128;       // [128]
    for (int i = tid; i < 1024; i += 256) {
        int row = i >> 3, s = i & 7;
        int t = t0 + row;
        at_s[i] = (t < TRR) ? g_attn[((size_t)(b * TRR + t)) * NSS_ + s] : 0.f;
    }
    for (int i = tid; i < 1024; i += 256) {
        int s = i >> 7, n = i & 127;
        ss_s[i] = g_newss[(b * NSS_ + s) * DD + n0 + n];
    }
    if (tid < 128) bv_s[tid] = bv[n0 + tid];
    __syncthreads();
    #pragma unroll
    for (int mi = 0; mi < 4; mi++)
        #pragma unroll
        for (int ni = 0; ni < 4; ni++) {
            int rl = wm * 64 + mi * 16 + (lane >> 2);
            int cl = wn * 32 + ni * 8 + (lane & 3) * 2;
            #pragma unroll
            for (int h = 0; h < 2; h++) {
                int row = rl + h * 8;
                int t = t0 + row;
                if (t < TRR) {
                    float u0 = 0.f, u1 = 0.f;
                    #pragma unroll
                    for (int s = 0; s < 8; s++) {
                        float aw = at_s[row * 8 + s];
                        u0 += aw * ss_s[s * 128 + cl];
                        u1 += aw * ss_s[s * 128 + cl + 1];
                    }
                    float v0 = acc[mi][ni][h * 2 + 0] + bv_s[cl] + u0;
                    float v1 = acc[mi][ni][h * 2 + 1] + bv_s[cl + 1] + u1;
                    float2 o;
                    o.x = fmaxf(v0, 0.f);
                    o.y = fmaxf(v1, 0.f);
                    *(float2*)(out + ((size_t)(b * TT + t)) * DD + n0 + cl) = o;
                }
            }
        }
}

// ---------------------------------------------------------------------------
extern "C" void kernel_launch(void* const* d_in, const int* in_sizes, int n_in,
                              void* d_out, int out_size) {
    const float* x   = (const float*)d_in[0];
    const float* Wq  = (const float*)d_in[1];
    const float* bq  = (const float*)d_in[2];
    const float* Wk  = (const float*)d_in[3];
    const float* bk  = (const float*)d_in[4];
    const float* Wv  = (const float*)d_in[5];
    const float* bv  = (const float*)d_in[6];
    const float* Wss = (const float*)d_in[7];
    const float* bss = (const float*)d_in[8];
    float* out = (float*)d_out;

    k_zero<<<(BB * DD + 255) / 256, 256>>>();
    k_convert_mean<<<dim3(64, BB), 192>>>(x);
    k_convert_wv<<<DD, 256>>>(Wv);
    k_prep<<<dim3(NSS_, BB), 256>>>(x, Wk, bk, Wss, bss, bq, out);
    k_wqss<<<dim3(24, BB), 256>>>(Wq);
    k_attn<<<(BB * (TRR / 8) + 7) / 8, 256>>>();
    cudaFuncSetAttribute(k_main, cudaFuncAttributeMaxDynamicSharedMemorySize, 81920);
    k_main<<<dim3(6, 32, BB), 256, 81920>>>(bv, out);
}

// round 3
// speedup vs baseline: 1.1241x; 1.1241x over previous
#include <cuda_runtime.h>
#include <cuda_bf16.h>
#include <cstdint>

#define BB 16
#define TT 4096
#define TRR 4088
#define DD 768
#define NSS_ 8
#define INNER_ 192
#define DKK 1536
#define SIM_SCALE 0.03608439182435161f  /* 1/sqrt(768) */

// ---------------- scratch (__device__ globals; no allocation allowed) -------
__device__ float g_psum[BB * 64 * DD];     // per-chunk column partial sums
__device__ float g_su[BB * DKK];
__device__ float g_newss[BB * NSS_ * DD];
__device__ float g_wqss[BB * DD * NSS_];   // [b][d][s]
__device__ float g_qb[BB * NSS_];
__device__ float g_attn[(size_t)BB * TRR * NSS_];
__device__ uint4 g_ahi4[(size_t)BB * TRR * DD / 8];   // bf16 hi of reg
__device__ uint4 g_alo4[(size_t)BB * TRR * DD / 8];   // bf16 lo of reg
__device__ uint4 g_wvThi4[DD * DD / 8];               // WvT [n][k] bf16 hi
__device__ uint4 g_wvTlo4[DD * DD / 8];               // WvT [n][k] bf16 lo

__device__ __forceinline__ uint32_t smem_u32(const void* p) {
    uint32_t a;
    asm("{ .reg .u64 t; cvta.to.shared.u64 t, %1; cvt.u32.u64 %0, t; }"
        : "=r"(a) : "l"(p));
    return a;
}
__device__ __forceinline__ void cpa16(uint32_t dst, const void* src, int ok) {
    int sz = ok ? 16 : 0;
    asm volatile("cp.async.cg.shared.global [%0], [%1], 16, %2;\n"
                 :: "r"(dst), "l"(src), "r"(sz) : "memory");
}

// ------- k_convert: fp32 x -> bf16 hi/lo + col partial sums; also Wv split --
// grid (64, 17): y<16 -> x conversion; y==16 -> Wv transpose+split.
__global__ void __launch_bounds__(192) k_convert(const float* __restrict__ x,
                                                 const float* __restrict__ Wv) {
    if (blockIdx.y == 16) {
        // Wv: rows k = blockIdx.x*12 .. +12
        __nv_bfloat16* th = (__nv_bfloat16*)g_wvThi4;
        __nv_bfloat16* tl = (__nv_bfloat16*)g_wvTlo4;
        int k0 = blockIdx.x * 12;
        for (int kk = 0; kk < 12; kk++) {
            int k = k0 + kk;
            for (int n = threadIdx.x; n < DD; n += 192) {
                float v = Wv[(size_t)k * DD + n];
                __nv_bfloat16 h = __float2bfloat16(v);
                __nv_bfloat16 l = __float2bfloat16(v - __bfloat162float(h));
                th[n * DD + k] = h;
                tl[n * DD + k] = l;
            }
        }
        return;
    }
    int b = blockIdx.y, c = blockIdx.x, tid = threadIdx.x;
    int d0 = tid * 4;
    __nv_bfloat16* ah = (__nv_bfloat16*)g_ahi4;
    __nv_bfloat16* al = (__nv_bfloat16*)g_alo4;
    float a0 = 0.f, a1 = 0.f, a2 = 0.f, a3 = 0.f;
    int t0 = c * 64;
    int tend = t0 + 64; if (tend > TRR) tend = TRR;
    for (int t = t0; t < tend; t++) {
        const float4 v = *(const float4*)(x + ((size_t)(b * TT + t)) * DD + d0);
        __nv_bfloat16 h0 = __float2bfloat16(v.x);
        __nv_bfloat16 h1 = __float2bfloat16(v.y);
        __nv_bfloat16 h2 = __float2bfloat16(v.z);
        __nv_bfloat16 h3 = __float2bfloat16(v.w);
        __nv_bfloat16 l0 = __float2bfloat16(v.x - __bfloat162float(h0));
        __nv_bfloat16 l1 = __float2bfloat16(v.y - __bfloat162float(h1));
        __nv_bfloat16 l2 = __float2bfloat16(v.z - __bfloat162float(h2));
        __nv_bfloat16 l3 = __float2bfloat16(v.w - __bfloat162float(h3));
        uint2 hp, lp;
        hp.x = (uint32_t)__bfloat16_as_ushort(h0) | ((uint32_t)__bfloat16_as_ushort(h1) << 16);
        hp.y = (uint32_t)__bfloat16_as_ushort(h2) | ((uint32_t)__bfloat16_as_ushort(h3) << 16);
        lp.x = (uint32_t)__bfloat16_as_ushort(l0) | ((uint32_t)__bfloat16_as_ushort(l1) << 16);
        lp.y = (uint32_t)__bfloat16_as_ushort(l2) | ((uint32_t)__bfloat16_as_ushort(l3) << 16);
        size_t idx = ((size_t)(b * TRR + t)) * DD + d0;
        *(uint2*)(ah + idx) = hp;
        *(uint2*)(al + idx) = lp;
        a0 += v.x; a1 += v.y; a2 += v.z; a3 += v.w;
    }
    float4 ps = make_float4(a0, a1, a2, a3);
    *(float4*)(g_psum + ((size_t)(b * 64 + c)) * DD + d0) = ps;
}

// ------- k_su: su[b][j] = bk[j] + sum_d mean[b][d] * Wk[d][j] ---------------
__global__ void __launch_bounds__(256) k_su(const float* __restrict__ Wk,
                                            const float* __restrict__ bk) {
    int b = blockIdx.y;
    int j = blockIdx.x * 256 + threadIdx.x;
    __shared__ float smn[DD];
    for (int d = threadIdx.x; d < DD; d += 256) {
        float s = 0.f;
        #pragma unroll 8
        for (int c = 0; c < 64; c++) s += g_psum[((size_t)(b * 64 + c)) * DD + d];
        smn[d] = s * (1.0f / (float)TRR);
    }
    __syncthreads();
    float a0 = 0.f, a1 = 0.f, a2 = 0.f, a3 = 0.f;
    #pragma unroll 4
    for (int d = 0; d < DD; d += 4) {
        a0 += smn[d + 0] * Wk[(size_t)(d + 0) * DKK + j];
        a1 += smn[d + 1] * Wk[(size_t)(d + 1) * DKK + j];
        a2 += smn[d + 2] * Wk[(size_t)(d + 2) * DKK + j];
        a3 += smn[d + 3] * Wk[(size_t)(d + 3) * DKK + j];
    }
    g_su[b * DKK + j] = (a0 + a1) + (a2 + a3) + bk[j];
}

// ------- k_newss: new_ss = x_ss + su @ Wss + bss; qb; output tail -----------
__global__ void __launch_bounds__(768) k_newss(
    const float* __restrict__ x, const float* __restrict__ Wss,
    const float* __restrict__ bss, const float* __restrict__ bq,
    float* __restrict__ out) {
    int b = blockIdx.x, j = threadIdx.x;
    __shared__ float ssu[DKK];
    __shared__ float red[NSS_ * 24];
    for (int i = j; i < DKK; i += 768) ssu[i] = g_su[b * DKK + i];
    __syncthreads();
    float acc[NSS_];
    #pragma unroll
    for (int s = 0; s < NSS_; s++)
        acc[s] = x[((size_t)(b * TT + TRR + s)) * DD + j] + bss[j];
    #pragma unroll 4
    for (int i = 0; i < INNER_; i++) {
        float w = Wss[(size_t)i * DD + j];
        #pragma unroll
        for (int s = 0; s < NSS_; s++) acc[s] += ssu[s * INNER_ + i] * w;
    }
    float bqj = bq[j];
    int warp = j >> 5;
    #pragma unroll
    for (int s = 0; s < NSS_; s++) {
        g_newss[(b * NSS_ + s) * DD + j] = acc[s];
        out[((size_t)(b * TT + TRR + s)) * DD + j] = acc[s];
        float p = bqj * acc[s];
        #pragma unroll
        for (int off = 16; off > 0; off >>= 1)
            p += __shfl_xor_sync(0xffffffffu, p, off);
        if ((j & 31) == 0) red[s * 24 + warp] = p;
    }
    __syncthreads();
    if (j < NSS_) {
        float q = 0.f;
        #pragma unroll
        for (int w = 0; w < 24; w++) q += red[j * 24 + w];
        g_qb[b * NSS_ + j] = q;
    }
}

// ------- k_wqss: Wq_ss[b][d][s] = sum_j Wq[d][j] * new_ss[b][s][j] ----------
__global__ void __launch_bounds__(256) k_wqss(const float* __restrict__ Wq) {
    int b = blockIdx.y, d0 = blockIdx.x * 32, tid = threadIdx.x;
    __shared__ float sn[NSS_ * 772];
    for (int i = tid; i < NSS_ * DD; i += 256) {
        int s = i / DD, j = i - s * DD;
        sn[s * 772 + j] = g_newss[(b * NSS_ + s) * DD + j];
    }
    __syncthreads();
    int s = tid & 7, d = d0 + (tid >> 3);
    const float* wr = Wq + (size_t)d * DD;
    const float* nr = sn + s * 772;
    float a0 = 0.f, a1 = 0.f, a2 = 0.f, a3 = 0.f;
    #pragma unroll 4
    for (int j = 0; j < DD; j += 4) {
        a0 += wr[j + 0] * nr[j + 0];
        a1 += wr[j + 1] * nr[j + 1];
        a2 += wr[j + 2] * nr[j + 2];
        a3 += wr[j + 3] * nr[j + 3];
    }
    g_wqss[(b * DD + d) * NSS_ + s] = (a0 + a1) + (a2 + a3);
}

// ------- k_attn: sim + softmax, warp handles 8 consecutive tokens -----------
__global__ void __launch_bounds__(256) k_attn() {
    int warp = (blockIdx.x * blockDim.x + threadIdx.x) >> 5;
    int lane = threadIdx.x & 31;
    if (warp >= BB * (TRR / 8)) return;
    int b = warp / (TRR / 8);
    int tok0 = (warp - b * (TRR / 8)) * 8;
    const __nv_bfloat16* ah = (const __nv_bfloat16*)g_ahi4;
    const __nv_bfloat16* al = (const __nv_bfloat16*)g_alo4;
    size_t base = ((size_t)(b * TRR + tok0)) * DD;
    const float4* wq = (const float4*)(g_wqss + (size_t)b * DD * NSS_);
    float sim[8][8];
    #pragma unroll
    for (int j = 0; j < 8; j++)
        #pragma unroll
        for (int s = 0; s < 8; s++) sim[j][s] = 0.f;
    #pragma unroll 2
    for (int i = 0; i < 24; i++) {
        int d = lane + i * 32;
        float4 w0 = wq[d * 2], w1 = wq[d * 2 + 1];
        float v[8];
        #pragma unroll
        for (int j = 0; j < 8; j++) {
            size_t idx = base + (size_t)j * DD + d;
            v[j] = __bfloat162float(ah[idx]) + __bfloat162float(al[idx]);
        }
        #pragma unroll
        for (int j = 0; j < 8; j++) {
            sim[j][0] += v[j] * w0.x; sim[j][1] += v[j] * w0.y;
            sim[j][2] += v[j] * w0.z; sim[j][3] += v[j] * w0.w;
            sim[j][4] += v[j] * w1.x; sim[j][5] += v[j] * w1.y;
            sim[j][6] += v[j] * w1.z; sim[j][7] += v[j] * w1.w;
        }
    }
    #pragma unroll
    for (int j = 0; j < 8; j++)
        #pragma unroll
        for (int s = 0; s < 8; s++)
            #pragma unroll
            for (int off = 16; off > 0; off >>= 1)
                sim[j][s] += __shfl_xor_sync(0xffffffffu, sim[j][s], off);
    if (lane < 8) {
        int j = lane;
        float p[8], m = -1e30f;
        #pragma unroll
        for (int s = 0; s < 8; s++) {
            p[s] = (sim[j][s] + g_qb[b * NSS_ + s]) * SIM_SCALE;
            m = fmaxf(m, p[s]);
        }
        float sum = 0.f;
        #pragma unroll
        for (int s = 0; s < 8; s++) { p[s] = expf(p[s] - m); sum += p[s]; }
        float inv = 1.f / sum;
        size_t ro = ((size_t)(b * TRR + tok0 + j)) * NSS_;
        #pragma unroll
        for (int s = 0; s < 8; s++) g_attn[ro + s] = p[s] * inv;
    }
}

// ------- k_main: split-bf16 HMMA GEMM, cp.async double-buffered -------------
// K-chunk = 64. Stage: Ah[128][72], Al, Bh, Bl (halves) = 73728 B; 2 stages.
// Epilogue region after stages: attn[128*9] + ss[8*128] + bv[128] floats.
#define PITCH 72
#define STG_ARR (128 * PITCH)            /* halves per array */
#define STG_SZ  (4 * STG_ARR * 2)        /* 73728 bytes per stage */
#define EP_OFF  (2 * STG_SZ)             /* 147456 */
#define SMEM_BYTES (EP_OFF + (128 * 9 + 8 * 128 + 128) * 4)
#define NCHUNK 12

#define MMA_BF16(Cr, Ar, Br)                                                   \
    asm volatile(                                                              \
        "mma.sync.aligned.m16n8k16.row.col.f32.bf16.bf16.f32 "                 \
        "{%0,%1,%2,%3},{%4,%5,%6,%7},{%8,%9},{%0,%1,%2,%3};\n"                 \
        : "+f"(Cr[0]), "+f"(Cr[1]), "+f"(Cr[2]), "+f"(Cr[3])                   \
        : "r"(Ar[0]), "r"(Ar[1]), "r"(Ar[2]), "r"(Ar[3]), "r"(Br[0]), "r"(Br[1]))

__global__ void __launch_bounds__(256, 1) k_main(const float* __restrict__ bv,
                                                 float* __restrict__ out) {
    extern __shared__ __align__(16) unsigned char smraw[];
    const uint32_t smb = smem_u32(smraw);
    const int tid = threadIdx.x, lane = tid & 31, wid = tid >> 5;
    const int wm = wid >> 2, wn = wid & 3;
    const int b = blockIdx.z, t0 = blockIdx.y * 128, n0 = blockIdx.x * 128;

    const char* gAh = (const char*)g_ahi4;
    const char* gAl = (const char*)g_alo4;
    const char* gBh = (const char*)g_wvThi4;
    const char* gBl = (const char*)g_wvTlo4;

    // loader: thread c in [0,2048): row=c>>4? No: per chunk 128 rows x 8 segs
    const int seg = tid & 7, r0 = tid >> 3;  // 32 rows per pass, 4 passes
    auto load_chunk = [&](int kt, int s) {
        const int k0 = kt * 64;
        const uint32_t base = smb + s * STG_SZ;
        #pragma unroll
        for (int i = 0; i < 4; i++) {
            int r = r0 + i * 32;
            uint32_t doff = (uint32_t)(r * PITCH + seg * 8) * 2;
            int t = t0 + r;
            int ok = (t < TRR);
            int tc = ok ? t : 0;
            size_t ai = (((size_t)(b * TRR + tc)) * DD + k0 + seg * 8) * 2;
            cpa16(base + doff,                  gAh + ai, ok);
            cpa16(base + STG_ARR * 2 + doff,    gAl + ai, ok);
            size_t bi = (((size_t)(n0 + r)) * DD + k0 + seg * 8) * 2;
            cpa16(base + STG_ARR * 4 + doff,    gBh + bi, 1);
            cpa16(base + STG_ARR * 6 + doff,    gBl + bi, 1);
        }
        asm volatile("cp.async.commit_group;\n" ::: "memory");
    };

    float acc[4][4][4];
    #pragma unroll
    for (int mi = 0; mi < 4; mi++)
        #pragma unroll
        for (int ni = 0; ni < 4; ni++)
            #pragma unroll
            for (int q = 0; q < 4; q++) acc[mi][ni][q] = 0.f;

    load_chunk(0, 0);
    for (int kt = 0; kt < NCHUNK; kt++) {
        const int buf = kt & 1;
        if (kt + 1 < NCHUNK) {
            load_chunk(kt + 1, buf ^ 1);
            asm volatile("cp.async.wait_group 1;\n" ::: "memory");
        } else {
            asm volatile("cp.async.wait_group 0;\n" ::: "memory");
        }
        __syncthreads();
        const __nv_bfloat16* As  = (const __nv_bfloat16*)(smraw + buf * STG_SZ);
        const __nv_bfloat16* Als = As + STG_ARR;
        const __nv_bfloat16* Bs  = As + 2 * STG_ARR;
        const __nv_bfloat16* Bls = As + 3 * STG_ARR;
        #pragma unroll
        for (int kk = 0; kk < 64; kk += 16) {
            uint32_t ra[4][4], la[4][4];
            #pragma unroll
            for (int mi = 0; mi < 4; mi++) {
                int r = wm * 64 + mi * 16 + (lane >> 2);
                int cc = kk + (lane & 3) * 2;
                const __nv_bfloat16* p = As + r * PITCH + cc;
                ra[mi][0] = *(const uint32_t*)(p);
                ra[mi][1] = *(const uint32_t*)(p + 8 * PITCH);
                ra[mi][2] = *(const uint32_t*)(p + 8);
                ra[mi][3] = *(const uint32_t*)(p + 8 * PITCH + 8);
                const __nv_bfloat16* q = Als + r * PITCH + cc;
                la[mi][0] = *(const uint32_t*)(q);
                la[mi][1] = *(const uint32_t*)(q + 8 * PITCH);
                la[mi][2] = *(const uint32_t*)(q + 8);
                la[mi][3] = *(const uint32_t*)(q + 8 * PITCH + 8);
            }
            uint32_t rb[4][2], lb[4][2];
            #pragma unroll
            for (int ni = 0; ni < 4; ni++) {
                int n = wn * 32 + ni * 8 + (lane >> 2);
                int kb = kk + (lane & 3) * 2;
                const __nv_bfloat16* p = Bs + n * PITCH + kb;
                rb[ni][0] = *(const uint32_t*)(p);
                rb[ni][1] = *(const uint32_t*)(p + 8);
                const __nv_bfloat16* q = Bls + n * PITCH + kb;
                lb[ni][0] = *(const uint32_t*)(q);
                lb[ni][1] = *(const uint32_t*)(q + 8);
            }
            #pragma unroll
            for (int mi = 0; mi < 4; mi++)
                #pragma unroll
                for (int ni = 0; ni < 4; ni++) {
                    MMA_BF16(acc[mi][ni], ra[mi], rb[ni]);
                    MMA_BF16(acc[mi][ni], ra[mi], lb[ni]);
                    MMA_BF16(acc[mi][ni], la[mi], rb[ni]);
                }
        }
        __syncthreads();
    }

    // ---- epilogue operands ----
    float* at_s = (float*)(smraw + EP_OFF);           // [128][9]
    float* ss_s = at_s + 128 * 9;                      // [8][128]
    float* bv_s = ss_s + 8 * 128;                      // [128]
    for (int i = tid; i < 1024; i += 256) {
        int r = i >> 3, s = i & 7;
        int t = t0 + r;
        at_s[r * 9 + s] = (t < TRR) ? g_attn[((size_t)(b * TRR + t)) * NSS_ + s] : 0.f;
    }
    for (int i = tid; i < 1024; i += 256) {
        int s = i >> 7, n = i & 127;
        ss_s[s * 128 + n] = g_newss[(b * NSS_ + s) * DD + n0 + n];
    }
    if (tid < 128) bv_s[tid] = bv[n0 + tid];
    __syncthreads();

    // ---- epilogue: relu(acc + bv + attn @ new_ss) ----
    #pragma unroll
    for (int mi = 0; mi < 4; mi++)
        #pragma unroll
        for (int ni = 0; ni < 4; ni++) {
            int rl = wm * 64 + mi * 16 + (lane >> 2);
            int cl = wn * 32 + ni * 8 + (lane & 3) * 2;
            #pragma unroll
            for (int h = 0; h < 2; h++) {
                int row = rl + h * 8;
                int t = t0 + row;
                if (t < TRR) {
                    float u0 = 0.f, u1 = 0.f;
                    #pragma unroll
                    for (int s = 0; s < 8; s++) {
                        float aw = at_s[row * 9 + s];
                        u0 += aw * ss_s[s * 128 + cl];
                        u1 += aw * ss_s[s * 128 + cl + 1];
                    }
                    float v0 = acc[mi][ni][h * 2 + 0] + bv_s[cl] + u0;
                    float v1 = acc[mi][ni][h * 2 + 1] + bv_s[cl + 1] + u1;
                    float2 o;
                    o.x = fmaxf(v0, 0.f);
                    o.y = fmaxf(v1, 0.f);
                    *(float2*)(out + ((size_t)(b * TT + t)) * DD + n0 + cl) = o;
                }
            }
        }
}

// ---------------------------------------------------------------------------
extern "C" void kernel_launch(void* const* d_in, const int* in_sizes, int n_in,
                              void* d_out, int out_size) {
    const float* x   = (const float*)d_in[0];
    const float* Wq  = (const float*)d_in[1];
    const float* bq  = (const float*)d_in[2];
    const float* Wk  = (const float*)d_in[3];
    const float* bk  = (const float*)d_in[4];
    const float* Wv  = (const float*)d_in[5];
    const float* bv  = (const float*)d_in[6];
    const float* Wss = (const float*)d_in[7];
    const float* bss = (const float*)d_in[8];
    float* out = (float*)d_out;

    k_convert<<<dim3(64, 17), 192>>>(x, Wv);
    k_su<<<dim3(6, BB), 256>>>(Wk, bk);
    k_newss<<<BB, 768>>>(x, Wss, bss, bq, out);
    k_wqss<<<dim3(24, BB), 256>>>(Wq);
    k_attn<<<(BB * (TRR / 8) + 7) / 8, 256>>>();
    cudaFuncSetAttribute(k_main, cudaFuncAttributeMaxDynamicSharedMemorySize, SMEM_BYTES);
    k_main<<<dim3(6, 32, BB), 256, SMEM_BYTES>>>(bv, out);
}